// round 2
// baseline (speedup 1.0000x reference)
#include <cuda_runtime.h>
#include <math.h>

#define SEQ 2048
#define DM  2048
#define NH  16
#define DQK 128
#define DV  128

// ---------------- scratch (device globals; no allocation allowed) ----------
__device__ float g_pq[NH * SEQ * DQK];   // 16 MB
__device__ float g_pk[NH * SEQ * DQK];   // 16 MB
__device__ float g_pv[NH * SEQ * DV];    // 16 MB
__device__ float g_ycat[SEQ * NH * DV];  // 16 MB  (row s, col h*128+v)
__device__ float g_sin[SEQ * 64];
__device__ float g_cos[SEQ * 64];

// ---------------- RoPE sin/cos table ---------------------------------------
// rate = theta * (-j/64)  (fp32, matching jnp order);  rot = s * rate (fp32)
// sin/cos computed in double on the exact fp32 rot (rot can be ~2e7 rad; needs
// full range reduction to match XLA's accurate fp32 sin).
__global__ void rope_table_kernel(const float* __restrict__ theta_p) {
    int idx = blockIdx.x * blockDim.x + threadIdx.x;
    if (idx >= SEQ * 64) return;
    int j = idx & 63;
    int s = idx >> 6;
    float theta = *theta_p;
    float rate = theta * (-(float)j / 64.0f);
    float rot  = (float)s * rate;
    double rd = (double)rot;
    g_sin[idx] = (float)sin(rd);
    g_cos[idx] = (float)cos(rd);
}

// ---------------- generic 128x128 tile SGEMM (fp32) -------------------------
// A: MxK row-major (lda), B: KxN row-major (ldb), C row-major (ldc).
// 256 threads, 8x8 micro-tile, BK=8.
__device__ __forceinline__ void sgemm_128x128(
    const float* __restrict__ A, int lda,
    const float* __restrict__ B, int ldb,
    float* __restrict__ C, int ldc,
    int K, int bm, int bn, float alpha)
{
    __shared__ float sA[8][132];
    __shared__ float sB[8][132];

    int tid = threadIdx.x;
    int tx = tid & 15;
    int ty = tid >> 4;

    float acc[8][8];
#pragma unroll
    for (int i = 0; i < 8; i++)
#pragma unroll
        for (int j = 0; j < 8; j++) acc[i][j] = 0.0f;

    int row_a = tid >> 1;          // 0..127
    int ka    = (tid & 1) * 4;     // 0 or 4
    int krow_b = tid >> 5;         // 0..7
    int nb     = (tid & 31) * 4;   // 0..124

    for (int k0 = 0; k0 < K; k0 += 8) {
        float4 av = *(const float4*)&A[(size_t)(bm + row_a) * lda + k0 + ka];
        float4 bv = *(const float4*)&B[(size_t)(k0 + krow_b) * ldb + bn + nb];
        __syncthreads();
        sA[ka + 0][row_a] = av.x;
        sA[ka + 1][row_a] = av.y;
        sA[ka + 2][row_a] = av.z;
        sA[ka + 3][row_a] = av.w;
        *(float4*)&sB[krow_b][nb] = bv;
        __syncthreads();
#pragma unroll
        for (int kk = 0; kk < 8; kk++) {
            float4 a0 = *(float4*)&sA[kk][ty * 4];
            float4 a1 = *(float4*)&sA[kk][64 + ty * 4];
            float4 b0 = *(float4*)&sB[kk][tx * 4];
            float4 b1 = *(float4*)&sB[kk][64 + tx * 4];
            float a[8] = {a0.x, a0.y, a0.z, a0.w, a1.x, a1.y, a1.z, a1.w};
            float b[8] = {b0.x, b0.y, b0.z, b0.w, b1.x, b1.y, b1.z, b1.w};
#pragma unroll
            for (int i = 0; i < 8; i++)
#pragma unroll
                for (int j = 0; j < 8; j++)
                    acc[i][j] = fmaf(a[i], b[j], acc[i][j]);
        }
    }

#pragma unroll
    for (int i = 0; i < 8; i++) {
        int r = bm + (i < 4 ? ty * 4 + i : 64 + ty * 4 + (i - 4));
        float4 o0 = make_float4(acc[i][0] * alpha, acc[i][1] * alpha,
                                acc[i][2] * alpha, acc[i][3] * alpha);
        float4 o1 = make_float4(acc[i][4] * alpha, acc[i][5] * alpha,
                                acc[i][6] * alpha, acc[i][7] * alpha);
        *(float4*)&C[(size_t)r * ldc + bn + tx * 4] = o0;
        *(float4*)&C[(size_t)r * ldc + bn + 64 + tx * 4] = o1;
    }
}

// ---------------- QKV projection -------------------------------------------
// grid: (16 m-tiles, 1, 48);  z -> (head, which)
__global__ void proj_kernel(const float* __restrict__ x,
                            const float* __restrict__ q,
                            const float* __restrict__ k,
                            const float* __restrict__ v) {
    int bz = blockIdx.z;
    int h = bz / 3;
    int which = bz - h * 3;
    const float* B = (which == 0 ? q : which == 1 ? k : v) + (size_t)h * DM * DQK;
    float* C = (which == 0 ? g_pq : which == 1 ? g_pk : g_pv) + (size_t)h * SEQ * DQK;
    sgemm_128x128(x, DM, B, DQK, C, DQK, DM, blockIdx.x * 128, 0, 1.0f);
}

// ---------------- RoPE apply (in place on g_pq / g_pk) ----------------------
__global__ void rope_apply_kernel() {
    int g = blockIdx.x * blockDim.x + threadIdx.x;   // 2^22 threads exactly
    int j = g & 63;
    int s = (g >> 6) & (SEQ - 1);
    int h = (g >> 17) & (NH - 1);
    int t = g >> 21;
    float* row = (t == 0 ? g_pq : g_pk) + ((size_t)h * SEQ + s) * DQK;
    float x1 = row[j];
    float x2 = row[j + 64];
    float sn = g_sin[s * 64 + j];
    float cs = g_cos[s * 64 + j];
    const float dq4 = 3.3635856610148585f;  // 128^0.25
    row[j]      = (cs * x1 - sn * x2) / dq4;
    row[j + 64] = (sn * x1 + cs * x2) / dq4;
}

// ---------------- flash attention ------------------------------------------
#define LQ 132
#define LK 68
#define LV 132
#define LP 132
#define ATTN_SMEM ((128 * LQ + 128 * LK + 64 * LV + 64 * LP) * 4)

extern __shared__ float attn_smem[];

__global__ void attn_kernel() {
    float* sQt = attn_smem;                 // [128 d][LQ]  (transposed Q)
    float* sKt = sQt + 128 * LQ;            // [128 d][LK]  (transposed K tile)
    float* sV  = sKt + 128 * LK;            // [64 k][LV]
    float* sPt = sV + 64 * LV;              // [64 k][LP]   (transposed P)

    int qt = blockIdx.x;
    int h  = blockIdx.y;
    int tid = threadIdx.x;
    int kx = tid & 15;    // also the d-column group for PV / epilogue
    int qy = tid >> 4;
    int q0 = qt * 128;

    const float* Q  = g_pq + ((size_t)h * SEQ + q0) * DQK;
    const float* Kb = g_pk + (size_t)h * SEQ * DQK;
    const float* Vb = g_pv + (size_t)h * SEQ * DV;

    // load Q tile transposed
#pragma unroll
    for (int it = 0; it < 16; it++) {
        int idx = it * 256 + tid;       // 0..4095 = 128 rows * 32 float4
        int qr = idx >> 5;
        int d0 = (idx & 31) * 4;
        float4 a = *(const float4*)&Q[qr * DQK + d0];
        sQt[(d0 + 0) * LQ + qr] = a.x;
        sQt[(d0 + 1) * LQ + qr] = a.y;
        sQt[(d0 + 2) * LQ + qr] = a.z;
        sQt[(d0 + 3) * LQ + qr] = a.w;
    }

    int rows[8];
#pragma unroll
    for (int i = 0; i < 8; i++)
        rows[i] = (i < 4 ? qy * 4 + i : 64 + qy * 4 + (i - 4));

    float m_run[8], l_run[8], y[8][8];
#pragma unroll
    for (int i = 0; i < 8; i++) {
        m_run[i] = -INFINITY;
        l_run[i] = 0.0f;
#pragma unroll
        for (int j = 0; j < 8; j++) y[i][j] = 0.0f;
    }

    int nkt = 2 * qt + 2;  // causal: only key tiles intersecting [0, q0+128)
    for (int kt = 0; kt < nkt; kt++) {
        int kbase = kt * 64;
        __syncthreads();
        // K tile transposed + V tile straight (64x128 each, 8 float4/thread)
#pragma unroll
        for (int it = 0; it < 8; it++) {
            int idx = it * 256 + tid;
            int kr = idx >> 5;
            int d0 = (idx & 31) * 4;
            float4 a = *(const float4*)&Kb[(size_t)(kbase + kr) * DQK + d0];
            sKt[(d0 + 0) * LK + kr] = a.x;
            sKt[(d0 + 1) * LK + kr] = a.y;
            sKt[(d0 + 2) * LK + kr] = a.z;
            sKt[(d0 + 3) * LK + kr] = a.w;
            *(float4*)&sV[kr * LV + d0] =
                *(const float4*)&Vb[(size_t)(kbase + kr) * DV + d0];
        }
        __syncthreads();

        // S = Q K^T  (128q x 64k tile; this thread: 8q x 4k)
        float acc[8][4];
#pragma unroll
        for (int i = 0; i < 8; i++)
#pragma unroll
            for (int j = 0; j < 4; j++) acc[i][j] = 0.0f;

#pragma unroll 8
        for (int d = 0; d < 128; d++) {
            float4 a0 = *(float4*)&sQt[d * LQ + qy * 4];
            float4 a1 = *(float4*)&sQt[d * LQ + 64 + qy * 4];
            float4 b  = *(float4*)&sKt[d * LK + kx * 4];
            float a[8] = {a0.x, a0.y, a0.z, a0.w, a1.x, a1.y, a1.z, a1.w};
            float bb[4] = {b.x, b.y, b.z, b.w};
#pragma unroll
            for (int i = 0; i < 8; i++)
#pragma unroll
                for (int j = 0; j < 4; j++)
                    acc[i][j] = fmaf(a[i], bb[j], acc[i][j]);
        }

        // online softmax (rows owned identically by this thread in S and Y)
        float corr[8];
#pragma unroll
        for (int i = 0; i < 8; i++) {
            int qg = q0 + rows[i];
#pragma unroll
            for (int j = 0; j < 4; j++) {
                int kg = kbase + kx * 4 + j;
                if (kg > qg) acc[i][j] -= 1.0e9f;  // matches reference mask
            }
            float mx = fmaxf(fmaxf(acc[i][0], acc[i][1]),
                             fmaxf(acc[i][2], acc[i][3]));
#pragma unroll
            for (int off = 8; off > 0; off >>= 1)
                mx = fmaxf(mx, __shfl_xor_sync(0xffffffffu, mx, off));
            float mnew = fmaxf(m_run[i], mx);
            float c = expf(m_run[i] - mnew);
            float ls = 0.0f;
#pragma unroll
            for (int j = 0; j < 4; j++) {
                float p = expf(acc[i][j] - mnew);
                ls += p;
                sPt[(kbase ? 0 : 0) + (kx * 4 + j) * LP + rows[i]] = p;
            }
#pragma unroll
            for (int off = 8; off > 0; off >>= 1)
                ls += __shfl_xor_sync(0xffffffffu, ls, off);
            l_run[i] = l_run[i] * c + ls;
            m_run[i] = mnew;
            corr[i] = c;
        }
#pragma unroll
        for (int i = 0; i < 8; i++)
#pragma unroll
            for (int j = 0; j < 8; j++) y[i][j] *= corr[i];

        __syncthreads();

        // Y += P @ V
#pragma unroll 4
        for (int k = 0; k < 64; k++) {
            float4 p0 = *(float4*)&sPt[k * LP + qy * 4];
            float4 p1 = *(float4*)&sPt[k * LP + 64 + qy * 4];
            float4 v0 = *(float4*)&sV[k * LV + kx * 4];
            float4 v1 = *(float4*)&sV[k * LV + 64 + kx * 4];
            float p[8]  = {p0.x, p0.y, p0.z, p0.w, p1.x, p1.y, p1.z, p1.w};
            float vv[8] = {v0.x, v0.y, v0.z, v0.w, v1.x, v1.y, v1.z, v1.w};
#pragma unroll
            for (int i = 0; i < 8; i++)
#pragma unroll
                for (int j = 0; j < 8; j++)
                    y[i][j] = fmaf(p[i], vv[j], y[i][j]);
        }
    }

    // epilogue: normalize, write into concatenated-head layout
#pragma unroll
    for (int i = 0; i < 8; i++) {
        float inv = 1.0f / l_run[i];
        int r = q0 + rows[i];
        float4 o0 = make_float4(y[i][0] * inv, y[i][1] * inv,
                                y[i][2] * inv, y[i][3] * inv);
        float4 o1 = make_float4(y[i][4] * inv, y[i][5] * inv,
                                y[i][6] * inv, y[i][7] * inv);
        size_t base = (size_t)r * (NH * DV) + h * DV;
        *(float4*)&g_ycat[base + kx * 4] = o0;
        *(float4*)&g_ycat[base + 64 + kx * 4] = o1;
    }
}

// ---------------- output projection ----------------------------------------
// Z = Ycat(2048x2048) @ Ocat(2048x2048) * (1/2048)
__global__ void out_gemm_kernel(const float* __restrict__ o, float* __restrict__ z) {
    sgemm_128x128(g_ycat, NH * DV, o, DM, z, DM, NH * DV,
                  blockIdx.x * 128, blockIdx.y * 128, 1.0f / 2048.0f);
}

// ---------------- launch ----------------------------------------------------
extern "C" void kernel_launch(void* const* d_in, const int* in_sizes, int n_in,
                              void* d_out, int out_size) {
    const float* x     = (const float*)d_in[0];
    const float* q     = (const float*)d_in[1];
    const float* k     = (const float*)d_in[2];
    const float* v     = (const float*)d_in[3];
    const float* o     = (const float*)d_in[4];
    const float* theta = (const float*)d_in[5];
    float* z = (float*)d_out;

    cudaFuncSetAttribute(attn_kernel,
                         cudaFuncAttributeMaxDynamicSharedMemorySize, ATTN_SMEM);

    rope_table_kernel<<<(SEQ * 64 + 255) / 256, 256>>>(theta);
    proj_kernel<<<dim3(16, 1, 48), 256>>>(x, q, k, v);
    rope_apply_kernel<<<(2 * NH * SEQ * 64) / 256, 256>>>();
    attn_kernel<<<dim3(16, NH), 256, ATTN_SMEM>>>();
    out_gemm_kernel<<<dim3(16, 16), 256>>>(o, z);
}

// round 7
// speedup vs baseline: 2.3191x; 2.3191x over previous
#include <cuda_runtime.h>
#include <cuda_bf16.h>
#include <math.h>
#include <cstdint>

#define SEQ 2048
#define DM  2048
#define NH  16
#define DQK 128
#define DV  128
#define NCAT 6144   // q|k|v concatenated head-columns

// ---------------- helpers ----------------------------------------------------
__device__ __forceinline__ uint32_t smem_u32(const void* p) {
    uint32_t a;
    asm("{ .reg .u64 t; cvta.to.shared.u64 t, %1; cvt.u32.u64 %0, t; }"
        : "=r"(a) : "l"(p));
    return a;
}

#define CP_ASYNC16(dst, src) \
    asm volatile("cp.async.cg.shared.global [%0], [%1], 16;" :: "r"(dst), "l"(src))
#define CP_COMMIT() asm volatile("cp.async.commit_group;" ::: "memory")
#define CP_WAIT(n)  asm volatile("cp.async.wait_group %0;" :: "n"(n) : "memory")

__device__ __forceinline__ void ldsm4(uint32_t* r, uint32_t addr) {
    asm volatile("ldmatrix.sync.aligned.m8n8.x4.shared.b16 {%0,%1,%2,%3}, [%4];"
                 : "=r"(r[0]), "=r"(r[1]), "=r"(r[2]), "=r"(r[3]) : "r"(addr));
}

__device__ __forceinline__ void mma_bf16(float* d, const uint32_t* a,
                                         uint32_t b0, uint32_t b1) {
    asm volatile(
        "mma.sync.aligned.m16n8k16.row.col.f32.bf16.bf16.f32 "
        "{%0,%1,%2,%3}, {%4,%5,%6,%7}, {%8,%9}, {%0,%1,%2,%3};"
        : "+f"(d[0]), "+f"(d[1]), "+f"(d[2]), "+f"(d[3])
        : "r"(a[0]), "r"(a[1]), "r"(a[2]), "r"(a[3]), "r"(b0), "r"(b1));
}

// ---------------- scratch (device globals) ----------------------------------
__device__ __align__(256) __nv_bfloat16 g_xs[2ull * SEQ * DM];    // 16 MB (2 planes)
__device__ __align__(256) __nv_bfloat16 g_wt[2ull * NCAT * DM];   // 50 MB
__device__ __align__(256) __nv_bfloat16 g_ot[2ull * DM * DM];     // 16 MB
__device__ __align__(256) __nv_bfloat16 g_ys[2ull * SEQ * DM];    // 16 MB
__device__ __align__(256) float g_pqkv[(size_t)SEQ * NCAT];       // 50 MB
__device__ __align__(256) float g_ycat[(size_t)SEQ * NH * DV];    // 16 MB
__device__ float g_sin[SEQ * 64];
__device__ float g_cos[SEQ * 64];

// ---------------- bf16x2 split ----------------------------------------------
__device__ __forceinline__ void split2(float x, __nv_bfloat16& b0, __nv_bfloat16& b1) {
    b0 = __float2bfloat16(x);
    float r = x - __bfloat162float(b0);
    b1 = __float2bfloat16(r);
}

// ---------------- RoPE sin/cos table ----------------------------------------
__global__ void rope_table_kernel(const float* __restrict__ theta_p) {
    int idx = blockIdx.x * blockDim.x + threadIdx.x;
    if (idx >= SEQ * 64) return;
    int j = idx & 63;
    int s = idx >> 6;
    float theta = *theta_p;
    float rate = theta * (-(float)j / 64.0f);
    float rot  = (float)s * rate;
    double rd = (double)rot;
    g_sin[idx] = (float)sin(rd);
    g_cos[idx] = (float)cos(rd);
}

// ---------------- split kernels ---------------------------------------------
__global__ void split_x_kernel(const float* __restrict__ x) {
    int i = blockIdx.x * blockDim.x + threadIdx.x;
    const size_t N = (size_t)SEQ * DM;
    __nv_bfloat16 b0, b1;
    split2(x[i], b0, b1);
    g_xs[i] = b0; g_xs[N + i] = b1;
}
__global__ void split_y_kernel() {
    int i = blockIdx.x * blockDim.x + threadIdx.x;
    const size_t N = (size_t)SEQ * DM;
    __nv_bfloat16 b0, b1;
    split2(g_ycat[i], b0, b1);
    g_ys[i] = b0; g_ys[N + i] = b1;
}

// ---------------- weight transpose + split ----------------------------------
// q/k/v[h][dm][e] -> g_wt[p][n = which*2048 + h*128 + e][dm]
__global__ void trans_w_kernel(const float* __restrict__ q,
                               const float* __restrict__ k,
                               const float* __restrict__ v) {
    __shared__ float t[32][33];
    int bz = blockIdx.z;
    int which = bz >> 4, h = bz & 15;
    const float* W = (which == 0 ? q : which == 1 ? k : v) + (size_t)h * DM * DQK;
    int kk0 = blockIdx.x * 32, e0 = blockIdx.y * 32;
    int tx = threadIdx.x, ty = threadIdx.y;
    const size_t WS = (size_t)NCAT * DM;
#pragma unroll
    for (int r = 0; r < 4; r++)
        t[ty + 8 * r][tx] = W[(size_t)(kk0 + ty + 8 * r) * DQK + e0 + tx];
    __syncthreads();
    size_t nbase = (size_t)which * 2048 + h * 128 + e0;
#pragma unroll
    for (int r = 0; r < 4; r++) {
        float xv = t[tx][ty + 8 * r];
        __nv_bfloat16 b0, b1;
        split2(xv, b0, b1);
        size_t o = (nbase + ty + 8 * r) * DM + kk0 + tx;
        g_wt[o] = b0; g_wt[WS + o] = b1;
    }
}
// o[h][v][dm] -> g_ot[p][n = dm][k = h*128 + v]
__global__ void trans_o_kernel(const float* __restrict__ o) {
    __shared__ float t[32][33];
    int h = blockIdx.z;
    const float* O = o + (size_t)h * DV * DM;
    int dm0 = blockIdx.x * 32, v0 = blockIdx.y * 32;
    int tx = threadIdx.x, ty = threadIdx.y;
    const size_t OS = (size_t)DM * DM;
#pragma unroll
    for (int r = 0; r < 4; r++)
        t[ty + 8 * r][tx] = O[(size_t)(v0 + ty + 8 * r) * DM + dm0 + tx];
    __syncthreads();
#pragma unroll
    for (int r = 0; r < 4; r++) {
        float xv = t[tx][ty + 8 * r];
        __nv_bfloat16 b0, b1;
        split2(xv, b0, b1);
        size_t oo = (size_t)(dm0 + ty + 8 * r) * DM + h * 128 + v0 + tx;
        g_ot[oo] = b0; g_ot[OS + oo] = b1;
    }
}

// ---------------- bf16x2 mma.sync GEMM ---------------------------------------
// C[m0:+256, n0:+128] = alpha * sum_k A[m][k]*B[n][k],  K=2048
// A,B each 2 bf16 planes, k-contiguous rows.
// CTA: 256 threads = 8 warps (wm 0..3 x wn 0..1), warp tile 64x64.
// smem per stage: A 2x32KB + B 2x16KB = 96KB; double buffered = 192KB.
#define GSM_BYTES (2 * 98304)

__global__ void __launch_bounds__(256, 1) gemm2_kernel(float* Cout, int mode) {
    extern __shared__ char gsm[];
    const __nv_bfloat16 *A3, *B3;
    size_t As, Bs;
    float* C; int ldc; float alpha;
    if (mode == 0) {
        A3 = g_xs; As = (size_t)SEQ * DM;
        B3 = g_wt; Bs = (size_t)NCAT * DM;
        C = g_pqkv; ldc = NCAT; alpha = 1.0f;
    } else {
        A3 = g_ys; As = (size_t)SEQ * DM;
        B3 = g_ot; Bs = (size_t)DM * DM;
        C = Cout; ldc = DM; alpha = 1.0f / 2048.0f;
    }

    uint32_t sb = smem_u32(gsm);
    int tid = threadIdx.x;
    int lane = tid & 31, wid = tid >> 5;
    int wm = wid >> 1, wn = wid & 1;
    int m0 = blockIdx.x * 256, n0 = blockIdx.y * 128;

    float acc[4][8][4];
#pragma unroll
    for (int i = 0; i < 4; i++)
#pragma unroll
        for (int j = 0; j < 8; j++)
#pragma unroll
            for (int r = 0; r < 4; r++) acc[i][j][r] = 0.0f;

    // ---- loader lambda (cp.async, swizzled stores) ----
    auto load_stage = [&](int s, int kc) {
        int k0 = kc * 64;
#pragma unroll
        for (int p = 0; p < 2; p++) {
            const __nv_bfloat16* gp = A3 + p * As + (size_t)m0 * DM + k0;
            uint32_t base = sb + s * 98304 + p * 32768;
#pragma unroll
            for (int i = 0; i < 8; i++) {
                int idx = i * 256 + tid;          // 0..2047
                int row = idx >> 3, c = idx & 7;
                uint32_t dst = base + row * 128 + ((c ^ (row & 7)) << 4);
                CP_ASYNC16(dst, gp + (size_t)row * DM + c * 8);
            }
        }
#pragma unroll
        for (int p = 0; p < 2; p++) {
            const __nv_bfloat16* gp = B3 + p * Bs + (size_t)n0 * DM + k0;
            uint32_t base = sb + s * 98304 + 65536 + p * 16384;
#pragma unroll
            for (int i = 0; i < 4; i++) {
                int idx = i * 256 + tid;          // 0..1023
                int row = idx >> 3, c = idx & 7;
                uint32_t dst = base + row * 128 + ((c ^ (row & 7)) << 4);
                CP_ASYNC16(dst, gp + (size_t)row * DM + c * 8);
            }
        }
    };

    load_stage(0, 0); CP_COMMIT();

    for (int kc = 0; kc < 32; kc++) {
        int s = kc & 1;
        if (kc + 1 < 32) { load_stage(s ^ 1, kc + 1); CP_COMMIT(); CP_WAIT(1); }
        else            { CP_WAIT(0); }
        __syncthreads();

        uint32_t stage = sb + s * 98304;
#pragma unroll
        for (int ks = 0; ks < 4; ks++) {
            uint32_t a[2][4][4];
#pragma unroll
            for (int p = 0; p < 2; p++)
#pragma unroll
                for (int mf = 0; mf < 4; mf++) {
                    int row = wm * 64 + mf * 16 + (lane & 15);
                    int c = ks * 2 + ((lane >> 4) & 1);
                    uint32_t addr = stage + p * 32768 + row * 128 +
                                    ((c ^ (row & 7)) << 4);
                    ldsm4(a[p][mf], addr);
                }
            uint32_t b[2][4][4];
#pragma unroll
            for (int p = 0; p < 2; p++)
#pragma unroll
                for (int nf2 = 0; nf2 < 4; nf2++) {
                    int row = wn * 64 + nf2 * 16 + (lane & 7) + ((lane >> 4) & 1) * 8;
                    int c = ks * 2 + ((lane >> 3) & 1);
                    uint32_t addr = stage + 65536 + p * 16384 + row * 128 +
                                    ((c ^ (row & 7)) << 4);
                    ldsm4(b[p][nf2], addr);
                }
            // products: (A0,B0), (A0,B1), (A1,B0)
#pragma unroll
            for (int mf = 0; mf < 4; mf++)
#pragma unroll
                for (int nf2 = 0; nf2 < 4; nf2++) {
                    mma_bf16(acc[mf][2 * nf2 + 0], a[0][mf], b[0][nf2][0], b[0][nf2][1]);
                    mma_bf16(acc[mf][2 * nf2 + 1], a[0][mf], b[0][nf2][2], b[0][nf2][3]);
                    mma_bf16(acc[mf][2 * nf2 + 0], a[0][mf], b[1][nf2][0], b[1][nf2][1]);
                    mma_bf16(acc[mf][2 * nf2 + 1], a[0][mf], b[1][nf2][2], b[1][nf2][3]);
                    mma_bf16(acc[mf][2 * nf2 + 0], a[1][mf], b[0][nf2][0], b[0][nf2][1]);
                    mma_bf16(acc[mf][2 * nf2 + 1], a[1][mf], b[0][nf2][2], b[0][nf2][3]);
                }
        }
        __syncthreads();
    }

    // epilogue
#pragma unroll
    for (int mf = 0; mf < 4; mf++) {
        int r0 = m0 + wm * 64 + mf * 16 + (lane >> 2);
#pragma unroll
        for (int nf = 0; nf < 8; nf++) {
            int cb = n0 + wn * 64 + nf * 8 + (lane & 3) * 2;
            float2 v01 = make_float2(acc[mf][nf][0] * alpha, acc[mf][nf][1] * alpha);
            float2 v23 = make_float2(acc[mf][nf][2] * alpha, acc[mf][nf][3] * alpha);
            *(float2*)&C[(size_t)r0 * ldc + cb] = v01;
            *(float2*)&C[(size_t)(r0 + 8) * ldc + cb] = v23;
        }
    }
}

// ---------------- RoPE apply (in place on q,k cols of g_pqkv) ----------------
__global__ void rope_apply_kernel() {
    int g = blockIdx.x * blockDim.x + threadIdx.x;   // 2^22 threads
    int j = g & 63;
    int s = (g >> 6) & (SEQ - 1);
    int h = (g >> 17) & (NH - 1);
    int t = g >> 21;                                  // 0=q, 1=k
    float* row = g_pqkv + (size_t)s * NCAT + t * 2048 + h * 128;
    float x1 = row[j];
    float x2 = row[j + 64];
    float sn = g_sin[s * 64 + j];
    float cs = g_cos[s * 64 + j];
    const float dq4 = 3.3635856610148585f;  // 128^0.25
    row[j]      = (cs * x1 - sn * x2) / dq4;
    row[j + 64] = (sn * x1 + cs * x2) / dq4;
}

// ---------------- flash attention (fp32 SIMT, LPT order) ---------------------
#define LQ 132
#define LK 68
#define LV 132
#define LP 132
#define ATTN_SMEM ((128 * LQ + 128 * LK + 64 * LV + 64 * LP) * 4)

__global__ void attn_kernel() {
    extern __shared__ float attn_smem[];
    float* sQt = attn_smem;
    float* sKt = sQt + 128 * LQ;
    float* sV  = sKt + 128 * LK;
    float* sPt = sV + 64 * LV;

    int h  = blockIdx.x;
    int qt = 15 - blockIdx.y;        // heavy q-tiles scheduled first (LPT)
    int tid = threadIdx.x;
    int kx = tid & 15;
    int qy = tid >> 4;
    int q0 = qt * 128;

    const float* Q  = g_pqkv + (size_t)q0 * NCAT + h * 128;
    const float* Kb = g_pqkv + 2048 + h * 128;
    const float* Vb = g_pqkv + 4096 + h * 128;

#pragma unroll
    for (int it = 0; it < 16; it++) {
        int idx = it * 256 + tid;
        int qr = idx >> 5;
        int d0 = (idx & 31) * 4;
        float4 a = *(const float4*)&Q[(size_t)qr * NCAT + d0];
        sQt[(d0 + 0) * LQ + qr] = a.x;
        sQt[(d0 + 1) * LQ + qr] = a.y;
        sQt[(d0 + 2) * LQ + qr] = a.z;
        sQt[(d0 + 3) * LQ + qr] = a.w;
    }

    int rows[8];
#pragma unroll
    for (int i = 0; i < 8; i++)
        rows[i] = (i < 4 ? qy * 4 + i : 64 + qy * 4 + (i - 4));

    float m_run[8], l_run[8], y[8][8];
#pragma unroll
    for (int i = 0; i < 8; i++) {
        m_run[i] = -INFINITY;
        l_run[i] = 0.0f;
#pragma unroll
        for (int j = 0; j < 8; j++) y[i][j] = 0.0f;
    }

    int nkt = 2 * qt + 2;
    for (int kt = 0; kt < nkt; kt++) {
        int kbase = kt * 64;
        __syncthreads();
#pragma unroll
        for (int it = 0; it < 8; it++) {
            int idx = it * 256 + tid;
            int kr = idx >> 5;
            int d0 = (idx & 31) * 4;
            float4 a = *(const float4*)&Kb[(size_t)(kbase + kr) * NCAT + d0];
            sKt[(d0 + 0) * LK + kr] = a.x;
            sKt[(d0 + 1) * LK + kr] = a.y;
            sKt[(d0 + 2) * LK + kr] = a.z;
            sKt[(d0 + 3) * LK + kr] = a.w;
            *(float4*)&sV[kr * LV + d0] =
                *(const float4*)&Vb[(size_t)(kbase + kr) * NCAT + d0];
        }
        __syncthreads();

        float acc[8][4];
#pragma unroll
        for (int i = 0; i < 8; i++)
#pragma unroll
            for (int j = 0; j < 4; j++) acc[i][j] = 0.0f;

#pragma unroll 8
        for (int d = 0; d < 128; d++) {
            float4 a0 = *(float4*)&sQt[d * LQ + qy * 4];
            float4 a1 = *(float4*)&sQt[d * LQ + 64 + qy * 4];
            float4 b  = *(float4*)&sKt[d * LK + kx * 4];
            float a[8] = {a0.x, a0.y, a0.z, a0.w, a1.x, a1.y, a1.z, a1.w};
            float bb[4] = {b.x, b.y, b.z, b.w};
#pragma unroll
            for (int i = 0; i < 8; i++)
#pragma unroll
                for (int j = 0; j < 4; j++)
                    acc[i][j] = fmaf(a[i], bb[j], acc[i][j]);
        }

        float corr[8];
#pragma unroll
        for (int i = 0; i < 8; i++) {
            int qg = q0 + rows[i];
#pragma unroll
            for (int j = 0; j < 4; j++) {
                int kg = kbase + kx * 4 + j;
                if (kg > qg) acc[i][j] -= 1.0e9f;
            }
            float mx = fmaxf(fmaxf(acc[i][0], acc[i][1]),
                             fmaxf(acc[i][2], acc[i][3]));
#pragma unroll
            for (int off = 8; off > 0; off >>= 1)
                mx = fmaxf(mx, __shfl_xor_sync(0xffffffffu, mx, off));
            float mnew = fmaxf(m_run[i], mx);
            float c = expf(m_run[i] - mnew);
            float ls = 0.0f;
#pragma unroll
            for (int j = 0; j < 4; j++) {
                float p = expf(acc[i][j] - mnew);
                ls += p;
                sPt[(kx * 4 + j) * LP + rows[i]] = p;
            }
#pragma unroll
            for (int off = 8; off > 0; off >>= 1)
                ls += __shfl_xor_sync(0xffffffffu, ls, off);
            l_run[i] = l_run[i] * c + ls;
            m_run[i] = mnew;
            corr[i] = c;
        }
#pragma unroll
        for (int i = 0; i < 8; i++)
#pragma unroll
            for (int j = 0; j < 8; j++) y[i][j] *= corr[i];

        __syncthreads();

#pragma unroll 4
        for (int k = 0; k < 64; k++) {
            float4 p0 = *(float4*)&sPt[k * LP + qy * 4];
            float4 p1 = *(float4*)&sPt[k * LP + 64 + qy * 4];
            float4 v0 = *(float4*)&sV[k * LV + kx * 4];
            float4 v1 = *(float4*)&sV[k * LV + 64 + kx * 4];
            float p[8]  = {p0.x, p0.y, p0.z, p0.w, p1.x, p1.y, p1.z, p1.w};
            float vv[8] = {v0.x, v0.y, v0.z, v0.w, v1.x, v1.y, v1.z, v1.w};
#pragma unroll
            for (int i = 0; i < 8; i++)
#pragma unroll
                for (int j = 0; j < 8; j++)
                    y[i][j] = fmaf(p[i], vv[j], y[i][j]);
        }
    }

#pragma unroll
    for (int i = 0; i < 8; i++) {
        float inv = 1.0f / l_run[i];
        int r = q0 + rows[i];
        float4 o0 = make_float4(y[i][0] * inv, y[i][1] * inv,
                                y[i][2] * inv, y[i][3] * inv);
        float4 o1 = make_float4(y[i][4] * inv, y[i][5] * inv,
                                y[i][6] * inv, y[i][7] * inv);
        size_t basep = (size_t)r * (NH * DV) + h * DV;
        *(float4*)&g_ycat[basep + kx * 4] = o0;
        *(float4*)&g_ycat[basep + 64 + kx * 4] = o1;
    }
}

// ---------------- launch ----------------------------------------------------
extern "C" void kernel_launch(void* const* d_in, const int* in_sizes, int n_in,
                              void* d_out, int out_size) {
    const float* x     = (const float*)d_in[0];
    const float* q     = (const float*)d_in[1];
    const float* k     = (const float*)d_in[2];
    const float* v     = (const float*)d_in[3];
    const float* o     = (const float*)d_in[4];
    const float* theta = (const float*)d_in[5];
    float* z = (float*)d_out;

    cudaFuncSetAttribute(attn_kernel,
                         cudaFuncAttributeMaxDynamicSharedMemorySize, ATTN_SMEM);
    cudaFuncSetAttribute(gemm2_kernel,
                         cudaFuncAttributeMaxDynamicSharedMemorySize, GSM_BYTES);

    rope_table_kernel<<<(SEQ * 64 + 255) / 256, 256>>>(theta);
    split_x_kernel<<<(SEQ * DM) / 256, 256>>>(x);
    trans_w_kernel<<<dim3(64, 4, 48), dim3(32, 8)>>>(q, k, v);
    trans_o_kernel<<<dim3(64, 4, 16), dim3(32, 8)>>>(o);
    gemm2_kernel<<<dim3(8, 48), 256, GSM_BYTES>>>(nullptr, 0);
    rope_apply_kernel<<<(2 * NH * SEQ * 64) / 256, 256>>>();
    attn_kernel<<<dim3(NH, 16), 256, ATTN_SMEM>>>();
    split_y_kernel<<<(SEQ * DM) / 256, 256>>>();
    gemm2_kernel<<<dim3(8, 16), 256, GSM_BYTES>>>(z, 1);
}